// round 8
// baseline (speedup 1.0000x reference)
#include <cuda_runtime.h>
#include <math.h>

// Problem constants: B=4, C=8, H=W=512
// pad = (int(sqrt(2)*512)-512)//2 + 1 = 107 ; padded = 726
#define BB 4
#define CC 8
#define HH 512
#define WW 512
#define PADC 107
#define PLANE (HH * WW)
#define DEG2RAD 0.017453292519943295f

#define TILE    64          // output tile per block (64x64)
#define BOX     96          // staged source region (rows/cols)
#define SSTRIDE 97          // smem row stride (floats) - bank spreading
#define THREADS 256

__global__ __launch_bounds__(THREADS)
void diff_pair_rotate_smem(const float* __restrict__ xin,
                           const float* __restrict__ yin,
                           const float* __restrict__ angles,
                           float* __restrict__ out)
{
    __shared__ float sm[BOX * SSTRIDE];   // 37,248 B static (one plane)

    const int tile = blockIdx.x;          // 0..63 (8x8 tiles)
    const int c    = blockIdx.y;          // channel
    const int b    = blockIdx.z;          // batch
    const int tx   = (tile & 7) * TILE;
    const int ty   = (tile >> 3) * TILE;

    const float rad = angles[b] * DEG2RAD;
    float sn, cs;
    sincosf(rad, &sn, &cs);

    // Collapsed linear source mapping:
    //   pxv = ox*step + d,  d = 107*step - 1,  step = 2/725
    //   gx  = pxv*cs - pyv*sn ;  gy = pxv*sn + pyv*cs
    //   ix_padded   = ((gx+1)*726 - 1)*0.5 = 363*gx + 362.5
    //   fx_unpadded = 363*gx + 362.5 - 107 = 363*gx + 255.5
    //   => fx = ox*Ax + oy*Bx + Cx   (and similarly fy)
    const float step = 2.0f / 725.0f;
    const float d    = (float)PADC * step - 1.0f;
    const float K    = 363.0f * step;
    const float Ax   =  K * cs;
    const float Bx   = -K * sn;
    const float Cx   = 363.0f * d * (cs - sn) + 255.5f;
    const float Ay   =  K * sn;
    const float By   =  K * cs;
    const float Cy   = 363.0f * d * (sn + cs) + 255.5f;

    // ---- bbox from the 4 tile corners (mapping is linear) ----
    const float xlo = (float)tx, xhi = (float)(tx + TILE - 1);
    const float ylo = (float)ty, yhi = (float)(ty + TILE - 1);
    const float fx00 = fmaf(xlo, Ax, fmaf(ylo, Bx, Cx));
    const float fx10 = fmaf(xhi, Ax, fmaf(ylo, Bx, Cx));
    const float fx01 = fmaf(xlo, Ax, fmaf(yhi, Bx, Cx));
    const float fx11 = fmaf(xhi, Ax, fmaf(yhi, Bx, Cx));
    const float fy00 = fmaf(xlo, Ay, fmaf(ylo, By, Cy));
    const float fy10 = fmaf(xhi, Ay, fmaf(ylo, By, Cy));
    const float fy01 = fmaf(xlo, Ay, fmaf(yhi, By, Cy));
    const float fy11 = fmaf(xhi, Ay, fmaf(yhi, By, Cy));

    const float fxmin = fminf(fminf(fx00, fx10), fminf(fx01, fx11));
    const float fymin = fminf(fminf(fy00, fy10), fminf(fy01, fy11));

    const int ox0 = (int)floorf(fxmin) - 1;   // 1-texel safety margin
    const int oy0 = (int)floorf(fymin) - 1;
    const float fox0 = (float)ox0;
    const float foy0 = (float)oy0;

    const int tid = threadIdx.x;
    const int lx  = tid & 63;                 // column within tile
    const int lyb = tid >> 6;                 // 0..3 row phase

    const size_t plane_off = ((size_t)(b * CC + c)) * PLANE;

    #pragma unroll
    for (int phase = 0; phase < 2; ++phase) {
        const float* __restrict__ src = (phase == 0 ? xin : yin) + plane_off;
        float* __restrict__ dst = out + plane_off
                                + (phase ? (size_t)(BB * CC) * PLANE : 0);

        if (phase) __syncthreads();           // buffer reuse barrier

        // ---- stage: coalesced rows, zero-fill outside the image ----
        #pragma unroll 1
        for (int i = tid; i < BOX * BOX; i += THREADS) {
            const unsigned r  = (unsigned)i / BOX;
            const unsigned cl = (unsigned)i - r * BOX;
            const int gx = ox0 + (int)cl;
            const int gy = oy0 + (int)r;
            float v = 0.0f;
            if (((unsigned)gx) < (unsigned)WW && ((unsigned)gy) < (unsigned)HH)
                v = __ldg(src + gy * WW + gx);
            sm[r * SSTRIDE + cl] = v;
        }
        __syncthreads();

        // ---- sample: branch-free bilinear from smem, 16 px/thread ----
        const float foxp = (float)(tx + lx);
        const float fxb = fmaf(foxp, Ax, Cx);   // column-constant parts
        const float fyb = fmaf(foxp, Ay, Cy);

        #pragma unroll 2
        for (int r = 0; r < 16; ++r) {
            const int oyp = ty + lyb + r * 4;
            const float foyp = (float)oyp;

            const float fx = fmaf(foyp, Bx, fxb);
            const float fy = fmaf(foyp, By, fyb);

            const float x0f = floorf(fx);
            const float y0f = floorf(fy);
            const float wx1 = fx - x0f, wx0 = 1.0f - wx1;
            const float wy1 = fy - y0f, wy0 = 1.0f - wy1;

            const int sx = (int)(x0f - fox0);   // in [0, BOX-2]
            const int sy = (int)(y0f - foy0);
            const int s00 = sy * SSTRIDE + sx;

            float acc =      sm[s00]                * (wx0 * wy0);
            acc = fmaf(sm[s00 + 1],           wx1 * wy0, acc);
            acc = fmaf(sm[s00 + SSTRIDE],     wx0 * wy1, acc);
            acc = fmaf(sm[s00 + SSTRIDE + 1], wx1 * wy1, acc);

            dst[oyp * WW + (tx + lx)] = acc;
        }
    }
}

extern "C" void kernel_launch(void* const* d_in, const int* in_sizes, int n_in,
                              void* d_out, int out_size)
{
    const float* x      = (const float*)d_in[0];
    const float* y      = (const float*)d_in[1];
    const float* angles = (const float*)d_in[2];
    float* out          = (float*)d_out;

    dim3 block(THREADS);
    dim3 grid(64, CC, BB);   // 8x8 tiles, 8 channels, 4 batches
    diff_pair_rotate_smem<<<grid, block>>>(x, y, angles, out);
}

// round 10
// speedup vs baseline: 1.2981x; 1.2981x over previous
#include <cuda_runtime.h>
#include <math.h>

// Problem constants: B=4, C=8, H=W=512
// pad = (int(sqrt(2)*512)-512)//2 + 1 = 107 ; padded = 726
#define BB 4
#define CC 8
#define HH 512
#define WW 512
#define PADC 107
#define PLANE (HH * WW)
#define DEG2RAD 0.017453292519943295f

// 32x32 block tile; warp footprint 8x4 (4x2 warps), 4 y-iterations/thread.
__global__ __launch_bounds__(256)
void diff_pair_rotate_gather(const float* __restrict__ xin,
                             const float* __restrict__ yin,
                             const float* __restrict__ angles,
                             float* __restrict__ out)
{
    const int b    = blockIdx.y;
    const int tile = blockIdx.x;              // 0..255 -> 16x16 tiles of 32x32
    const int tx   = (tile & 15) << 5;
    const int ty   = (tile >> 4) << 5;

    const int lane = threadIdx.x & 31;
    const int warp = threadIdx.x >> 5;        // 0..7
    const int px   = tx + ((warp & 3) << 3) + (lane & 7);   // 8-wide lane run
    const int py0  = ty + ((warp >> 2) << 2) + (lane >> 3); // 4 rows per warp

    const float rad = angles[b] * DEG2RAD;
    float sn, cs;
    sincosf(rad, &sn, &cs);

    // Collapsed affine source map (verified R8: rel_err 6.5e-5):
    //   fx = px*Ax + py*Bx + Cx ; fy = px*Ay + py*By + Cy   (unpadded coords)
    const float step = 2.0f / 725.0f;
    const float d    = (float)PADC * step - 1.0f;
    const float K    = 363.0f * step;
    const float Ax   =  K * cs;
    const float Bx   = -K * sn;
    const float Cx   = 363.0f * d * (cs - sn) + 255.5f;
    const float Ay   =  K * sn;
    const float By   =  K * cs;
    const float Cy   = 363.0f * d * (sn + cs) + 255.5f;

    const float fpx = (float)px;
    const float fxc = fmaf(fpx, Ax, Cx);      // column-constant parts
    const float fyc = fmaf(fpx, Ay, Cy);

    const float* __restrict__ xb = xin + (size_t)(b * CC) * PLANE;
    const float* __restrict__ yb = yin + (size_t)(b * CC) * PLANE;
    float* __restrict__ outx = out + (size_t)(b * CC) * PLANE;
    float* __restrict__ outy = out + (size_t)(BB * CC) * PLANE
                                   + (size_t)(b * CC) * PLANE;

    #pragma unroll 1
    for (int it = 0; it < 4; ++it) {
        const int py = py0 + (it << 3);       // rows py0, py0+8, +16, +24
        const float fpy = (float)py;
        const float fx = fmaf(fpy, Bx, fxc);
        const float fy = fmaf(fpy, By, fyc);

        const float x0f = floorf(fx);
        const float y0f = floorf(fy);
        const float wx1 = fx - x0f, wx0 = 1.0f - wx1;
        const float wy1 = fy - y0f, wy0 = 1.0f - wy1;

        const int xs0 = (int)x0f;
        const int ys0 = (int)y0f;

        // zero padding + padding_mode='zeros' collapse to one bounds check
        const bool vx0 = ((unsigned)xs0)       < (unsigned)WW;
        const bool vx1 = ((unsigned)(xs0 + 1)) < (unsigned)WW;
        const bool vy0 = ((unsigned)ys0)       < (unsigned)HH;
        const bool vy1 = ((unsigned)(ys0 + 1)) < (unsigned)HH;
        const bool v00 = vx0 & vy0;
        const bool v10 = vx1 & vy0;
        const bool v01 = vx0 & vy1;
        const bool v11 = vx1 & vy1;

        const float w00 = wx0 * wy0;
        const float w10 = wx1 * wy0;
        const float w01 = wx0 * wy1;
        const float w11 = wx1 * wy1;

        const int i00 = ys0 * WW + xs0;
        const int oi  = py * WW + px;

        #pragma unroll 4
        for (int c = 0; c < CC; ++c) {
            const float* __restrict__ xp = xb + c * PLANE;
            const float* __restrict__ yp = yb + c * PLANE;

            float ax = 0.0f, ay = 0.0f;
            if (v00) { ax = fmaf(__ldg(xp + i00),          w00, ax);
                       ay = fmaf(__ldg(yp + i00),          w00, ay); }
            if (v10) { ax = fmaf(__ldg(xp + i00 + 1),      w10, ax);
                       ay = fmaf(__ldg(yp + i00 + 1),      w10, ay); }
            if (v01) { ax = fmaf(__ldg(xp + i00 + WW),     w01, ax);
                       ay = fmaf(__ldg(yp + i00 + WW),     w01, ay); }
            if (v11) { ax = fmaf(__ldg(xp + i00 + WW + 1), w11, ax);
                       ay = fmaf(__ldg(yp + i00 + WW + 1), w11, ay); }

            outx[c * PLANE + oi] = ax;
            outy[c * PLANE + oi] = ay;
        }
    }
}

extern "C" void kernel_launch(void* const* d_in, const int* in_sizes, int n_in,
                              void* d_out, int out_size)
{
    const float* x      = (const float*)d_in[0];
    const float* y      = (const float*)d_in[1];
    const float* angles = (const float*)d_in[2];
    float* out          = (float*)d_out;

    dim3 block(256);
    dim3 grid(256, BB);     // 16x16 tiles of 32x32, 4 batches
    diff_pair_rotate_gather<<<grid, block>>>(x, y, angles, out);
}

// round 12
// speedup vs baseline: 1.9093x; 1.4708x over previous
#include <cuda_runtime.h>
#include <math.h>

// Problem constants: B=4, C=8, H=W=512
// pad = (int(sqrt(2)*512)-512)//2 + 1 = 107 ; padded = 726
#define BB 4
#define CC 8
#define HH 512
#define WW 512
#define PADC 107
#define PLANE (HH * WW)
#define DEG2RAD 0.017453292519943295f

// Block tile 64x4 (=256 px, 1 px/thread); 8 warps: 4 across x, 2 across y,
// each warp footprint 16x2.
__global__ __launch_bounds__(256)
void diff_pair_rotate_gather(const float* __restrict__ xin,
                             const float* __restrict__ yin,
                             const float* __restrict__ angles,
                             float* __restrict__ out)
{
    const int b    = blockIdx.y;
    const int tile = blockIdx.x;              // 0..1023 -> 8x128 tiles of 64x4
    const int tx   = (tile & 7) << 6;
    const int ty   = (tile >> 3) << 2;

    const int lane = threadIdx.x & 31;
    const int warp = threadIdx.x >> 5;        // 0..7
    const int px   = tx + ((warp & 3) << 4) + (lane & 15);  // 16-wide run
    const int py   = ty + ((warp >> 2) << 1) + (lane >> 4); // rows ty+0..3

    const float rad = angles[b] * DEG2RAD;
    float sn, cs;
    sincosf(rad, &sn, &cs);

    // Collapsed affine source map (validated R8/R10: rel_err 6.5e-5):
    //   fx = px*Ax + py*Bx + Cx ; fy = px*Ay + py*By + Cy (unpadded coords)
    const float step = 2.0f / 725.0f;
    const float d    = (float)PADC * step - 1.0f;
    const float K    = 363.0f * step;
    const float Ax   =  K * cs;
    const float Bx   = -K * sn;
    const float Cx   = 363.0f * d * (cs - sn) + 255.5f;
    const float Ay   =  K * sn;
    const float By   =  K * cs;
    const float Cy   = 363.0f * d * (sn + cs) + 255.5f;

    const float fx = fmaf((float)py, Bx, fmaf((float)px, Ax, Cx));
    const float fy = fmaf((float)py, By, fmaf((float)px, Ay, Cy));

    const float x0f = floorf(fx);
    const float y0f = floorf(fy);
    const float wx1 = fx - x0f, wx0 = 1.0f - wx1;
    const float wy1 = fy - y0f, wy0 = 1.0f - wy1;

    const int xs0 = (int)x0f;
    const int ys0 = (int)y0f;

    // zero padding + padding_mode='zeros' collapse to one bounds check
    const bool vx0 = ((unsigned)xs0)       < (unsigned)WW;
    const bool vx1 = ((unsigned)(xs0 + 1)) < (unsigned)WW;
    const bool vy0 = ((unsigned)ys0)       < (unsigned)HH;
    const bool vy1 = ((unsigned)(ys0 + 1)) < (unsigned)HH;
    const bool v00 = vx0 & vy0;
    const bool v10 = vx1 & vy0;
    const bool v01 = vx0 & vy1;
    const bool v11 = vx1 & vy1;

    const float w00 = wx0 * wy0;
    const float w10 = wx1 * wy0;
    const float w01 = wx0 * wy1;
    const float w11 = wx1 * wy1;

    const int i00 = ys0 * WW + xs0;
    const int oi  = py * WW + px;

    const float* __restrict__ xb = xin + (size_t)(b * CC) * PLANE;
    const float* __restrict__ yb = yin + (size_t)(b * CC) * PLANE;
    float* __restrict__ outx = out + (size_t)(b * CC) * PLANE + oi;
    float* __restrict__ outy = out + (size_t)(BB * CC) * PLANE
                                   + (size_t)(b * CC) * PLANE + oi;

    #pragma unroll 4
    for (int c = 0; c < CC; ++c) {
        const float* __restrict__ xp = xb + c * PLANE;
        const float* __restrict__ yp = yb + c * PLANE;

        float ax = 0.0f, ay = 0.0f;
        if (v00) { ax = fmaf(__ldg(xp + i00),          w00, ax);
                   ay = fmaf(__ldg(yp + i00),          w00, ay); }
        if (v10) { ax = fmaf(__ldg(xp + i00 + 1),      w10, ax);
                   ay = fmaf(__ldg(yp + i00 + 1),      w10, ay); }
        if (v01) { ax = fmaf(__ldg(xp + i00 + WW),     w01, ax);
                   ay = fmaf(__ldg(yp + i00 + WW),     w01, ay); }
        if (v11) { ax = fmaf(__ldg(xp + i00 + WW + 1), w11, ax);
                   ay = fmaf(__ldg(yp + i00 + WW + 1), w11, ay); }

        outx[c * PLANE] = ax;
        outy[c * PLANE] = ay;
    }
}

extern "C" void kernel_launch(void* const* d_in, const int* in_sizes, int n_in,
                              void* d_out, int out_size)
{
    const float* x      = (const float*)d_in[0];
    const float* y      = (const float*)d_in[1];
    const float* angles = (const float*)d_in[2];
    float* out          = (float*)d_out;

    dim3 block(256);
    dim3 grid(1024, BB);    // 8x128 tiles of 64x4, 4 batches
    diff_pair_rotate_gather<<<grid, block>>>(x, y, angles, out);
}